// round 3
// baseline (speedup 1.0000x reference)
#include <cuda_runtime.h>

#define M_ 4
#define B_ 2048
#define D_ 1024
#define O_ 1024
#define E_ 8
#define C_ 2

// Folded per-expert head: g_fold_w[e][d][c] = sum_o expert_w[e][d][o] * head_w[o][c]
__device__ float g_fold_w[E_ * D_ * C_];   // 64 KB
__device__ float g_fold_b[E_ * C_];
__device__ float g_gate_t[E_ * D_];        // transposed gate: [E][D], 32 KB

__device__ __forceinline__ float wsum(float v) {
#pragma unroll
  for (int o = 16; o; o >>= 1) v += __shfl_xor_sync(0xffffffffu, v, o);
  return v;
}

// ---------------------------------------------------------------------------
// Kernel A: fold expert_w / expert_b through head_w; transpose gate_w.
// bid < 512 : weight rows, 2 rows per warp. bid==512: bias. bid==513: gate^T.
// ---------------------------------------------------------------------------
__global__ __launch_bounds__(256) void fold_kernel(
    const float* __restrict__ expert_w,
    const float* __restrict__ expert_b,
    const float* __restrict__ gate_w,
    const float* __restrict__ head_w) {
  const int bid = blockIdx.x;
  if (bid == 513) {  // transpose gate_w [D,E] -> g_gate_t [E,D]
    for (int t = threadIdx.x; t < E_ * D_; t += 256) {
      int d = t >> 3, e = t & 7;
      g_gate_t[e * D_ + d] = gate_w[t];
    }
    return;
  }
  __shared__ float4 sh[O_ * C_ / 4];  // head_w staged: 8 KB
  for (int t = threadIdx.x; t < O_ * C_ / 4; t += 256)
    sh[t] = reinterpret_cast<const float4*>(head_w)[t];
  __syncthreads();

  const int warp = threadIdx.x >> 5;
  const int lane = threadIdx.x & 31;

  if (bid < 512) {
    const int r0 = bid * 16 + warp * 2;
    const float4* s0 = reinterpret_cast<const float4*>(expert_w) + (size_t)r0 * (O_ / 4);
    const float4* s1 = s0 + (O_ / 4);
    float a00 = 0.f, a01 = 0.f, a10 = 0.f, a11 = 0.f;
#pragma unroll
    for (int i = 0; i < 8; i++) {
      int o = i * 128 + lane * 4;
      float4 w0 = s0[o >> 2], w1 = s1[o >> 2];
      float4 h0 = sh[o >> 1], h1 = sh[(o >> 1) + 1];
      a00 += w0.x * h0.x + w0.y * h0.z + w0.z * h1.x + w0.w * h1.z;
      a01 += w0.x * h0.y + w0.y * h0.w + w0.z * h1.y + w0.w * h1.w;
      a10 += w1.x * h0.x + w1.y * h0.z + w1.z * h1.x + w1.w * h1.z;
      a11 += w1.x * h0.y + w1.y * h0.w + w1.z * h1.y + w1.w * h1.w;
    }
    a00 = wsum(a00); a01 = wsum(a01); a10 = wsum(a10); a11 = wsum(a11);
    if (lane == 0) {
      reinterpret_cast<float2*>(g_fold_w)[r0]     = make_float2(a00, a01);
      reinterpret_cast<float2*>(g_fold_w)[r0 + 1] = make_float2(a10, a11);
    }
  } else if (warp < E_) {  // bid == 512: bias fold
    const float4* s = reinterpret_cast<const float4*>(expert_b) + warp * (O_ / 4);
    float a0 = 0.f, a1 = 0.f;
#pragma unroll
    for (int i = 0; i < 8; i++) {
      int o = i * 128 + lane * 4;
      float4 w = s[o >> 2];
      float4 h0 = sh[o >> 1], h1 = sh[(o >> 1) + 1];
      a0 += w.x * h0.x + w.y * h0.z + w.z * h1.x + w.w * h1.z;
      a1 += w.x * h0.y + w.y * h0.w + w.z * h1.y + w.w * h1.w;
    }
    a0 = wsum(a0); a1 = wsum(a1);
    if (lane == 0)
      reinterpret_cast<float2*>(g_fold_b)[warp] = make_float2(a0, a1);
  }
}

// Routed folded dot for one instance: reduce its 8 logit partials, pick the
// winner, dot x against the folded [D,2] expert, warp-reduce, add folded bias.
__device__ __forceinline__ float2 route_one(
    const float* acc, const float4* xr4, const float4* fold4,
    const float* __restrict__ gate_b, int lane) {
  float l[E_];
#pragma unroll
  for (int e = 0; e < E_; e++) l[e] = wsum(acc[e]) + gate_b[e];

  // winner = max index among two largest logits (jax top_k ties -> lower idx)
  int i1 = 0; float v1 = l[0];
#pragma unroll
  for (int e = 1; e < E_; e++) if (l[e] > v1) { v1 = l[e]; i1 = e; }
  int i2 = 0; float v2 = -3.402823466e38f;
#pragma unroll
  for (int e = 0; e < E_; e++)
    if (e != i1 && l[e] > v2) { v2 = l[e]; i2 = e; }
  const int winner = (i1 > i2) ? i1 : i2;

  const float4* fw = fold4 + winner * (D_ * C_ / 4);
  float y0 = 0.f, y1 = 0.f;
#pragma unroll
  for (int ch = 0; ch < 8; ch++) {
    float4 xr = xr4[ch * 32 + lane];                 // reload: L1 hit
    float4 f0 = fw[ch * 64 + lane * 2];
    float4 f1 = fw[ch * 64 + lane * 2 + 1];
    y0 += xr.x * f0.x + xr.y * f0.z + xr.z * f1.x + xr.w * f1.z;
    y1 += xr.x * f0.y + xr.y * f0.w + xr.z * f1.y + xr.w * f1.w;
  }
  y0 = wsum(y0) + g_fold_b[winner * C_ + 0];
  y1 = wsum(y1) + g_fold_b[winner * C_ + 1];
  return make_float2(y0, y1);
}

// ---------------------------------------------------------------------------
// Kernel B: 1024 blocks x 128 threads. Each warp = one batch column x one
// modality pair (2 instances -> acc[2][8] = 16 regs). Block covers 2 batch
// columns; cross-m combine via smem.
// ---------------------------------------------------------------------------
__global__ __launch_bounds__(128, 6) void moe_kernel(
    const float* __restrict__ x,
    const float* __restrict__ gate_b,
    const float* __restrict__ head_b,
    float* __restrict__ out) {
  const int warp = threadIdx.x >> 5;
  const int lane = threadIdx.x & 31;
  const int b    = blockIdx.x * 2 + (warp >> 1);
  const int m0   = (warp & 1) * 2;            // modality pair {m0, m0+1}

  const float4* x4    = reinterpret_cast<const float4*>(x);
  const float4* gate4 = reinterpret_cast<const float4*>(g_gate_t);
  const float4* fold4 = reinterpret_cast<const float4*>(g_fold_w);

  const float4* xa4 = x4 + ((size_t)m0 * B_ + b) * (D_ / 4);
  const float4* xb4 = xa4 + (size_t)B_ * (D_ / 4);

  float acc0[E_], acc1[E_];
#pragma unroll
  for (int e = 0; e < E_; e++) { acc0[e] = 0.f; acc1[e] = 0.f; }

  // Phase 1: gate logit partials for both instances; gate loads amortized 2x
  // within the warp and L1-resident (32 KB) across all warps.
#pragma unroll
  for (int ch = 0; ch < 8; ch++) {
    float4 xa = xa4[ch * 32 + lane];
    float4 xb = xb4[ch * 32 + lane];
#pragma unroll
    for (int e = 0; e < E_; e++) {
      float4 g = gate4[e * (D_ / 4) + ch * 32 + lane];
      acc0[e] += xa.x * g.x + xa.y * g.y + xa.z * g.z + xa.w * g.w;
      acc1[e] += xb.x * g.x + xb.y * g.y + xb.z * g.z + xb.w * g.w;
    }
  }

  // Phase 2: route + folded dot per instance; sum over the m-pair.
  float2 ya = route_one(acc0, xa4, fold4, gate_b, lane);
  float2 yb = route_one(acc1, xb4, fold4, gate_b, lane);

  __shared__ float2 part[4];
  if (lane == 0) part[warp] = make_float2(ya.x + yb.x, ya.y + yb.y);
  __syncthreads();

  if (threadIdx.x < 2) {
    float2 p0 = part[threadIdx.x * 2 + 0];
    float2 p1 = part[threadIdx.x * 2 + 1];
    int bb = blockIdx.x * 2 + threadIdx.x;
    reinterpret_cast<float2*>(out)[bb] =
        make_float2(0.25f * (p0.x + p1.x) + head_b[0],
                    0.25f * (p0.y + p1.y) + head_b[1]);
  }
}

// ---------------------------------------------------------------------------
// Inputs (metadata order): x, gate_w, gate_b, expert_w, expert_b, head_w, head_b
// ---------------------------------------------------------------------------
extern "C" void kernel_launch(void* const* d_in, const int* in_sizes, int n_in,
                              void* d_out, int out_size) {
  const float* x        = (const float*)d_in[0];
  const float* gate_w   = (const float*)d_in[1];
  const float* gate_b   = (const float*)d_in[2];
  const float* expert_w = (const float*)d_in[3];
  const float* expert_b = (const float*)d_in[4];
  const float* head_w   = (const float*)d_in[5];
  const float* head_b   = (const float*)d_in[6];
  float* out = (float*)d_out;

  fold_kernel<<<514, 256>>>(expert_w, expert_b, gate_w, head_w);
  moe_kernel<<<B_ / 2, 128>>>(x, gate_b, head_b, out);
}